// round 5
// baseline (speedup 1.0000x reference)
#include <cuda_runtime.h>

// HyperPatch: b=16, c=8, h=w=512, fh=fw=16, c_out=8, sc=64, K=3, PAD=1
// R5: (a) conv: weights pre-duplicated in smem for f32x2, pixel-pair
//     accumulators -> aligned input pairs free from LDS.128 (ALU packs 20->8).
//     (b) kernel1: tiled GEMM with smem staging (s no longer re-read 72x).

#define N_TILES 4096
__device__ float g_wpp[N_TILES * 576];   // scratch: [n][o] natural order

// ---- f32x2 helpers ---------------------------------------------------------
__device__ __forceinline__ unsigned long long ffma2(
    unsigned long long a, unsigned long long b, unsigned long long c)
{
    unsigned long long d;
    asm("fma.rn.f32x2 %0, %1, %2, %3;" : "=l"(d) : "l"(a), "l"(b), "l"(c));
    return d;
}
__device__ __forceinline__ unsigned long long pack2(float x)
{
    unsigned long long d;
    asm("mov.b64 %0, {%1, %1};" : "=l"(d) : "f"(x));
    return d;
}
// (hi of a, lo of b): builds pair (in[p+1], in[p+2]) from (in[p],in[p+1]),(in[p+2],in[p+3])
__device__ __forceinline__ unsigned long long oddpair(
    unsigned long long a, unsigned long long b)
{
    unsigned long long d;
    asm("{\n\t.reg .b32 al, ah, bl, bh;\n\t"
        "mov.b64 {al, ah}, %1;\n\t"
        "mov.b64 {bl, bh}, %2;\n\t"
        "mov.b64 %0, {ah, bl};\n\t}"
        : "=l"(d) : "l"(a), "l"(b));
    return d;
}

// ---------------------------------------------------------------------------
// Kernel 1: g_wpp[4096 x 576] = S[4096 x 64] @ w_s2w^T, tiled.
// grid (32 n-blocks, 9 o-chunks), 256 threads.
// CTA: 128 n x 64 o. Thread: 2 n x 16 o (8 o-pairs, f32x2).
// ---------------------------------------------------------------------------
__global__ __launch_bounds__(256) void hyper_weights_kernel(
    const float* __restrict__ w_s2w,   // [576][64]
    const float* __restrict__ s_in)    // [16][64][16][16] = [16][64][256]
{
    __shared__ float s_sm[64][128];                 // [s][n-local] 32 KB
    __shared__ __align__(16) float w_sm[64][64];    // [s][o-local] 16 KB

    const int t  = threadIdx.x;
    const int n0 = blockIdx.x * 128;
    const int o0 = blockIdx.y * 64;
    const int b  = n0 >> 8;
    const int f0 = n0 & 255;                        // 0 or 128

    for (int i = t; i < 64 * 128; i += 256) {
        int s  = i >> 7;
        int nn = i & 127;
        s_sm[s][nn] = s_in[b * 16384 + s * 256 + f0 + nn];
    }
    for (int i = t; i < 64 * 64; i += 256) {
        int o = i >> 6;
        int s = i & 63;
        w_sm[s][o] = w_s2w[(o0 + o) * 64 + s];
    }
    __syncthreads();

    const int tn = t & 63;      // n = n0 + 2*tn (+0/1)
    const int to = t >> 6;      // o group: o0 + to*16 .. +15

    unsigned long long acc[2][8];
#pragma unroll
    for (int j = 0; j < 2; j++)
#pragma unroll
        for (int k = 0; k < 8; k++) acc[j][k] = 0ull;

#pragma unroll 4
    for (int s = 0; s < 64; s++) {
        float2 a = *reinterpret_cast<const float2*>(&s_sm[s][2 * tn]);
        unsigned long long a0 = pack2(a.x);
        unsigned long long a1 = pack2(a.y);
        const ulonglong2* wp =
            reinterpret_cast<const ulonglong2*>(&w_sm[s][to * 16]);
        ulonglong2 wA = wp[0];   // o-pairs (0,1),(2,3)
        ulonglong2 wB = wp[1];   // o-pairs (4,5),(6,7)
        acc[0][0] = ffma2(a0, wA.x, acc[0][0]);
        acc[0][1] = ffma2(a0, wA.y, acc[0][1]);
        acc[0][2] = ffma2(a0, wB.x, acc[0][2]);
        acc[0][3] = ffma2(a0, wB.y, acc[0][3]);
        wA = wp[2];  wB = wp[3];
        acc[0][4] = ffma2(a0, wA.x, acc[0][4]);
        acc[0][5] = ffma2(a0, wA.y, acc[0][5]);
        acc[0][6] = ffma2(a0, wB.x, acc[0][6]);
        acc[0][7] = ffma2(a0, wB.y, acc[0][7]);
        wA = wp[0];  wB = wp[1];
        acc[1][0] = ffma2(a1, wA.x, acc[1][0]);
        acc[1][1] = ffma2(a1, wA.y, acc[1][1]);
        acc[1][2] = ffma2(a1, wB.x, acc[1][2]);
        acc[1][3] = ffma2(a1, wB.y, acc[1][3]);
        wA = wp[2];  wB = wp[3];
        acc[1][4] = ffma2(a1, wA.x, acc[1][4]);
        acc[1][5] = ffma2(a1, wA.y, acc[1][5]);
        acc[1][6] = ffma2(a1, wB.x, acc[1][6]);
        acc[1][7] = ffma2(a1, wB.y, acc[1][7]);
    }

#pragma unroll
    for (int j = 0; j < 2; j++) {
        float* dst = g_wpp + (size_t)(n0 + 2 * tn + j) * 576 + o0 + to * 16;
#pragma unroll
        for (int k = 0; k < 8; k++)
            *reinterpret_cast<unsigned long long*>(dst + 2 * k) = acc[j][k];
    }
}

// ---------------------------------------------------------------------------
// Kernel 2: per-tile 3x3 conv. grid = 4096 tiles, 256 threads.
// Thread: 4 c_out (half by t>>7) x 8 px, accumulated as 4co x 4 pixel-pair
// f32x2 registers. Weights duplicated in smem -> FFMA2 operands direct
// from LDS; even input pairs direct from LDS.128; odd pairs via 4 recombines.
// ---------------------------------------------------------------------------
__global__ __launch_bounds__(256, 4) void hyper_conv_kernel(
    const float* __restrict__ x,       // [16][8][512][512]
    float* __restrict__ out)           // [16][8][512][512]
{
    __shared__ float sin_s[8][34][36];                         // 38.25 KB
    __shared__ __align__(16) unsigned long long wsm2[72][8];   // dup pairs, 4.5 KB

    const int n  = blockIdx.x;
    const int t  = threadIdx.x;
    const int b  = n >> 8;
    const int fy = (n >> 4) & 15;
    const int fx = n & 15;

    // stage weights duplicated: g_wpp[n][co*72 + kidx] -> wsm2[kidx][co] = (v,v)
    const float* wpp_n = g_wpp + (size_t)n * 576;
    for (int i = t; i < 576; i += 256) {
        int co   = i / 72;
        int kidx = i - co * 72;
        float v  = wpp_n[i];
        *reinterpret_cast<float2*>(&wsm2[kidx][co]) = make_float2(v, v);
    }

    // stage 34x34x8 reflect-padded input window
    const float* xb  = x + (size_t)b * (8 * 512 * 512);
    const int row0 = fy * 32 - 1;
    const int col0 = fx * 32 - 1;
    for (int i = t; i < 8 * 34 * 34; i += 256) {
        int ci  = i / 1156;
        int rem = i - ci * 1156;
        int r   = rem / 34;
        int cl  = rem - r * 34;
        int gr = row0 + r;  gr = gr < 0 ? -gr : (gr > 511 ? 1022 - gr : gr);
        int gc = col0 + cl; gc = gc < 0 ? -gc : (gc > 511 ? 1022 - gc : gc);
        sin_s[ci][r][cl] = xb[(ci << 18) + (gr << 9) + gc];
    }
    __syncthreads();

    const int cohalf = t >> 7;          // 0: co 0-3, 1: co 4-7
    const int tt  = t & 127;
    const int py  = tt >> 2;            // 0..31
    const int px0 = (tt & 3) << 3;      // 0,8,16,24

    unsigned long long acc2[4][4];      // [co within half][pixel-pair]
#pragma unroll
    for (int c = 0; c < 4; c++)
#pragma unroll
        for (int p = 0; p < 4; p++) acc2[c][p] = 0ull;

#pragma unroll 1
    for (int ci = 0; ci < 8; ci++) {
#pragma unroll
        for (int kr = 0; kr < 3; kr++) {
            const float* rowp = &sin_s[ci][py + kr][px0];
            ulonglong2 U0 = *reinterpret_cast<const ulonglong2*>(rowp);     // (0,1),(2,3)
            ulonglong2 U1 = *reinterpret_cast<const ulonglong2*>(rowp + 4); // (4,5),(6,7)
            unsigned long long P8 =
                *reinterpret_cast<const unsigned long long*>(rowp + 8);     // (8,9)
            unsigned long long pr[3][4];
            pr[0][0] = U0.x;  pr[0][1] = U0.y;  pr[0][2] = U1.x;  pr[0][3] = U1.y;
            pr[1][0] = oddpair(U0.x, U0.y);
            pr[1][1] = oddpair(U0.y, U1.x);
            pr[1][2] = oddpair(U1.x, U1.y);
            pr[1][3] = oddpair(U1.y, P8);
            pr[2][0] = U0.y;  pr[2][1] = U1.x;  pr[2][2] = U1.y;  pr[2][3] = P8;

            const int kbase = ci * 9 + kr * 3;
#pragma unroll
            for (int kc = 0; kc < 3; kc++) {
                const ulonglong2* wp = reinterpret_cast<const ulonglong2*>(
                    &wsm2[kbase + kc][cohalf * 4]);
                ulonglong2 wA = wp[0];   // (w_co0,w_co0),(w_co1,w_co1)
                ulonglong2 wB = wp[1];   // (w_co2,w_co2),(w_co3,w_co3)
#pragma unroll
                for (int p = 0; p < 4; p++) {
                    acc2[0][p] = ffma2(wA.x, pr[kc][p], acc2[0][p]);
                    acc2[1][p] = ffma2(wA.y, pr[kc][p], acc2[1][p]);
                    acc2[2][p] = ffma2(wB.x, pr[kc][p], acc2[2][p]);
                    acc2[3][p] = ffma2(wB.y, pr[kc][p], acc2[3][p]);
                }
            }
        }
    }

    const int gy = (fy << 5) + py;
    const int gx = (fx << 5) + px0;
    const int co_base = b * 8 + cohalf * 4;
#pragma unroll
    for (int c = 0; c < 4; c++) {
        float* op = out + (((size_t)(co_base + c)) << 18) + (gy << 9) + gx;
#pragma unroll
        for (int p = 0; p < 4; p++)
            *reinterpret_cast<unsigned long long*>(op + 2 * p) = acc2[c][p];
    }
}

// ---------------------------------------------------------------------------
extern "C" void kernel_launch(void* const* d_in, const int* in_sizes, int n_in,
                              void* d_out, int out_size)
{
    (void)in_sizes; (void)n_in; (void)out_size;
    const float* x     = (const float*)d_in[0];   // [16,8,512,512]
    const float* s     = (const float*)d_in[1];   // [16,64,16,16]
    const float* w_s2w = (const float*)d_in[2];   // [576,64]
    float* out = (float*)d_out;                   // [16,8,512,512]

    hyper_weights_kernel<<<dim3(32, 9), 256>>>(w_s2w, s);
    hyper_conv_kernel<<<N_TILES, 256>>>(x, out);
}